// round 2
// baseline (speedup 1.0000x reference)
#include <cuda_runtime.h>

// SSL2d: per-channel sub-pixel shift with bilinear interpolation, zero padding.
// x: [B=32, C=384, H=56, W=56] fp32; a,b: [C] fp32 shifts.
// out[n,c,h,w] = bilinear sample of x[n,c] at (h + a[c], w + b[c]), zero outside.

#define B_ 32
#define C_ 384
#define H_ 56
#define W_ 56
#define HW_ (H_ * W_)          // 3136
#define THREADS 256

__global__ __launch_bounds__(THREADS)
void ssl2d_kernel(const float* __restrict__ x,
                  const float* __restrict__ a,
                  const float* __restrict__ b,
                  float* __restrict__ out) {
    __shared__ float s[HW_];   // 12544 B: one (n,c) plane

    const int plane = blockIdx.x;          // n * C + c
    const int c = plane % C_;

    const float* __restrict__ xp = x + (size_t)plane * HW_;
    float* __restrict__ op       = out + (size_t)plane * HW_;

    // Coalesced plane load: 3136 floats = 784 float4, fully contiguous.
    {
        const float4* __restrict__ x4 = (const float4*)xp;
        float4* s4 = (float4*)s;
        #pragma unroll
        for (int i = threadIdx.x; i < HW_ / 4; i += THREADS)
            s4[i] = x4[i];
    }

    // Per-channel constant shift decomposition.
    const float av = __ldg(&a[c]);
    const float bv = __ldg(&b[c]);
    const float iaf = floorf(av);
    const float ibf = floorf(bv);
    const float fa = av - iaf;
    const float fb = bv - ibf;
    const int ia = (int)iaf;
    const int ib = (int)ibf;
    const float w00 = (1.0f - fa) * (1.0f - fb);
    const float w01 = (1.0f - fa) * fb;
    const float w10 = fa * (1.0f - fb);
    const float w11 = fa * fb;

    __syncthreads();

    // Each thread produces 4 outputs along w and stores one float4.
    // HW_/4 = 784 vector outputs; 256 threads -> 3-4 iterations.
    for (int i4 = threadIdx.x; i4 < HW_ / 4; i4 += THREADS) {
        const int lin = i4 * 4;
        const int h = lin / W_;
        const int wbase = lin - h * W_;    // 0..52, row-aligned since 56 % 4 == 0

        const int h0 = h + ia;
        const int h1 = h0 + 1;
        const bool vh0 = (unsigned)h0 < (unsigned)H_;
        const bool vh1 = (unsigned)h1 < (unsigned)H_;
        const int h0r = vh0 ? h0 * W_ : 0;
        const int h1r = vh1 ? h1 * W_ : 0;

        float r[4];
        #pragma unroll
        for (int j = 0; j < 4; ++j) {
            const int w0 = wbase + j + ib;
            const int w1 = w0 + 1;
            const bool vw0 = (unsigned)w0 < (unsigned)W_;
            const bool vw1 = (unsigned)w1 < (unsigned)W_;
            const int w0c = vw0 ? w0 : 0;
            const int w1c = vw1 ? w1 : 0;

            const float v00 = (vh0 && vw0) ? s[h0r + w0c] : 0.0f;
            const float v01 = (vh0 && vw1) ? s[h0r + w1c] : 0.0f;
            const float v10 = (vh1 && vw0) ? s[h1r + w0c] : 0.0f;
            const float v11 = (vh1 && vw1) ? s[h1r + w1c] : 0.0f;

            r[j] = w00 * v00 + w01 * v01 + w10 * v10 + w11 * v11;
        }

        float4 o;
        o.x = r[0]; o.y = r[1]; o.z = r[2]; o.w = r[3];
        *(float4*)(op + lin) = o;
    }
}

extern "C" void kernel_launch(void* const* d_in, const int* in_sizes, int n_in,
                              void* d_out, int out_size) {
    const float* x = (const float*)d_in[0];
    const float* a = (const float*)d_in[1];
    const float* b = (const float*)d_in[2];
    float* out = (float*)d_out;

    ssl2d_kernel<<<B_ * C_, THREADS>>>(x, a, b, out);
}

// round 3
// speedup vs baseline: 1.7191x; 1.7191x over previous
#include <cuda_runtime.h>

// SSL2d: per-channel sub-pixel shift with bilinear interpolation, zero padding.
// x: [B=32, C=384, H=56, W=56] fp32; a,b: [C] fp32 shifts.
// out[n,c,h,w] = bilinear sample of x[n,c] at (h + a[c], w + b[c]), zero outside.
//
// R2: column-strip mapping (lane <-> w, conflict-free LDS) + vertical register
// reuse of the row-interpolated value (2 LDS per output instead of 4, no bank
// conflicts instead of 4-way). Previous kernel was L1tex-bound at 91.5%.

#define B_ 32
#define C_ 384
#define H_ 56
#define W_ 56
#define HW_ (H_ * W_)          // 3136
#define THREADS 256
#define STRIPS 4               // 4 h-strips of 14 rows
#define ROWS_PER_STRIP (H_ / STRIPS)   // 14

__global__ __launch_bounds__(THREADS)
void ssl2d_kernel(const float* __restrict__ x,
                  const float* __restrict__ a,
                  const float* __restrict__ b,
                  float* __restrict__ out) {
    __shared__ float s[HW_];   // 12544 B: one (n,c) plane

    const int plane = blockIdx.x;          // n * C + c
    const int c = plane % C_;

    const float* __restrict__ xp = x + (size_t)plane * HW_;
    float* __restrict__ op       = out + (size_t)plane * HW_;

    // Coalesced plane load: 3136 floats = 784 float4, fully contiguous.
    {
        const float4* __restrict__ x4 = (const float4*)xp;
        float4* s4 = (float4*)s;
        #pragma unroll
        for (int i = threadIdx.x; i < HW_ / 4; i += THREADS)
            s4[i] = x4[i];
    }

    // Per-channel constant shift decomposition.
    const float av = __ldg(&a[c]);
    const float bv = __ldg(&b[c]);
    const float iaf = floorf(av);
    const float ibf = floorf(bv);
    const float fa = av - iaf;             // fractional h weight
    const float fb = bv - ibf;             // fractional w weight
    const int ia = (int)iaf;
    const int ib = (int)ibf;

    __syncthreads();

    // Thread mapping: strip = tid/64 (14 rows), w = tid%64 (active w < 56).
    // Lanes within a warp map to consecutive w -> conflict-free LDS, and no
    // warp straddles a strip boundary.
    const int w     = threadIdx.x & 63;
    const int strip = threadIdx.x >> 6;

    if (w < W_) {
        // Horizontal taps for this column (constant down the strip).
        const int w0 = w + ib;
        const int w1 = w0 + 1;
        const bool vw0 = (unsigned)w0 < (unsigned)W_;
        const bool vw1 = (unsigned)w1 < (unsigned)W_;
        const int w0c = vw0 ? w0 : 0;
        const int w1c = vw1 ? w1 : 0;
        // Fold the w-validity masks into the horizontal weights.
        const float mw0 = vw0 ? (1.0f - fb) : 0.0f;
        const float mw1 = vw1 ? fb : 0.0f;
        const float ga  = 1.0f - fa;

        const int hstart = strip * ROWS_PER_STRIP;

        // Row-interpolated sample at source row hh (0 outside the image).
        auto rowcomb = [&](int hh) -> float {
            if ((unsigned)hh >= (unsigned)H_) return 0.0f;
            const int r = hh * W_;
            return mw0 * s[r + w0c] + mw1 * s[r + w1c];
        };

        float rlo = rowcomb(hstart + ia);
        #pragma unroll
        for (int i = 0; i < ROWS_PER_STRIP; ++i) {
            const int h = hstart + i;
            const float rhi = rowcomb(h + ia + 1);
            op[h * W_ + w] = ga * rlo + fa * rhi;
            rlo = rhi;     // bottom row-pair of step h is top of step h+1
        }
    }
}

extern "C" void kernel_launch(void* const* d_in, const int* in_sizes, int n_in,
                              void* d_out, int out_size) {
    const float* x = (const float*)d_in[0];
    const float* a = (const float*)d_in[1];
    const float* b = (const float*)d_in[2];
    float* out = (float*)d_out;

    ssl2d_kernel<<<B_ * C_, THREADS>>>(x, a, b, out);
}